// round 3
// baseline (speedup 1.0000x reference)
#include <cuda_runtime.h>
#include <stdint.h>

// Inputs (metadata order):
//  0: vertex_dofs  [V,1]  f32
//  1: edge_dofs    [E,2]  f32
//  2: face_dofs    [C,1]  f32
//  3: y            [C,10,16] f32
//  4: faces        [C,3]  i32
//  5: faces_to_edges [C,3] i32
//  6: edge_orientation [C,3] i32
// Output: [C,16] f32

#define NB 10
#define QPTS 16
#define CELLS_PER_BLOCK 64
#define THREADS 256  // 4 threads per cell

__global__ __launch_bounds__(THREADS)
void quadfn_kernel(const float* __restrict__ vertex_dofs,
                   const float* __restrict__ edge_dofs,
                   const float* __restrict__ face_dofs,
                   const float* __restrict__ y,
                   const int*   __restrict__ faces,
                   const int*   __restrict__ f2e,
                   const int*   __restrict__ orient,
                   float*       __restrict__ out,
                   int C)
{
    __shared__ float s_local[CELLS_PER_BLOCK][NB];

    const int tid = threadIdx.x;
    const int block_cell0 = blockIdx.x * CELLS_PER_BLOCK;

    // ---- Phase 1: gather local dofs, one thread per cell (tid < 64) ----
    if (tid < CELLS_PER_BLOCK) {
        int c = block_cell0 + tid;
        if (c < C) {
            // vertex dofs (DV=1)
            int v0 = faces[3 * c + 0];
            int v1 = faces[3 * c + 1];
            int v2 = faces[3 * c + 2];
            s_local[tid][0] = __ldg(&vertex_dofs[v0]);
            s_local[tid][1] = __ldg(&vertex_dofs[v1]);
            s_local[tid][2] = __ldg(&vertex_dofs[v2]);

            // edge dofs (DE=2), flip when orientation == 0
            #pragma unroll
            for (int e = 0; e < 3; e++) {
                int   eidx = f2e[3 * c + e];
                int   o    = orient[3 * c + e];
                float2 ed  = __ldg((const float2*)edge_dofs + eidx);
                float a = (o != 0) ? ed.x : ed.y;
                float b = (o != 0) ? ed.y : ed.x;
                s_local[tid][3 + 2 * e]     = a;
                s_local[tid][3 + 2 * e + 1] = b;
            }

            // face dof (DF=1)
            s_local[tid][9] = face_dofs[c];
        }
    }
    __syncthreads();

    // ---- Phase 2: contraction. 4 threads per cell, one float4 (4 q) each ----
    const int cell_in_blk = tid >> 2;   // 0..63
    const int qg          = tid & 3;    // which float4 of Q=16
    const int c           = block_cell0 + cell_in_blk;
    if (c >= C) return;

    const float4* yv = reinterpret_cast<const float4*>(y + (size_t)c * NB * QPTS) + qg;
    // per-b stride in float4 units: QPTS/4 = 4

    float4 acc = make_float4(0.f, 0.f, 0.f, 0.f);
    #pragma unroll
    for (int b = 0; b < NB; b++) {
        float  w = s_local[cell_in_blk][b];
        float4 v = yv[b * (QPTS / 4)];
        acc.x = fmaf(w, v.x, acc.x);
        acc.y = fmaf(w, v.y, acc.y);
        acc.z = fmaf(w, v.z, acc.z);
        acc.w = fmaf(w, v.w, acc.w);
    }

    reinterpret_cast<float4*>(out + (size_t)c * QPTS)[qg] = acc;
}

extern "C" void kernel_launch(void* const* d_in, const int* in_sizes, int n_in,
                              void* d_out, int out_size)
{
    const float* vertex_dofs = (const float*)d_in[0];
    const float* edge_dofs   = (const float*)d_in[1];
    const float* face_dofs   = (const float*)d_in[2];
    const float* y           = (const float*)d_in[3];
    const int*   faces       = (const int*)d_in[4];
    const int*   f2e         = (const int*)d_in[5];
    const int*   orient      = (const int*)d_in[6];
    float*       out         = (float*)d_out;

    // Derive C from y: [C, NB, Q]
    int C = in_sizes[3] / (NB * QPTS);

    int blocks = (C + CELLS_PER_BLOCK - 1) / CELLS_PER_BLOCK;
    quadfn_kernel<<<blocks, THREADS>>>(vertex_dofs, edge_dofs, face_dofs, y,
                                       faces, f2e, orient, out, C);
}

// round 5
// speedup vs baseline: 1.0826x; 1.0826x over previous
#include <cuda_runtime.h>
#include <stdint.h>

// Inputs (metadata order):
//  0: vertex_dofs  [V,1]  f32
//  1: edge_dofs    [E,2]  f32
//  2: face_dofs    [C,1]  f32
//  3: y            [C,10,16] f32
//  4: faces        [C,3]  i32
//  5: faces_to_edges [C,3] i32
//  6: edge_orientation [C,3] i32
// Output: [C,16] f32

#define NB 10
#define QPTS 16
#define CELLS_PER_BLOCK 64
#define THREADS 256  // 4 threads per cell, one float4 (4 quad pts) each

__global__ __launch_bounds__(THREADS)
void quadfn_kernel(const float* __restrict__ vertex_dofs,
                   const float* __restrict__ edge_dofs,
                   const float* __restrict__ face_dofs,
                   const float* __restrict__ y,
                   const int*   __restrict__ faces,
                   const int*   __restrict__ f2e,
                   const int*   __restrict__ orient,
                   float*       __restrict__ out,
                   int C)
{
    __shared__ float s_local[CELLS_PER_BLOCK][NB];

    const int tid         = threadIdx.x;
    const int block_cell0 = blockIdx.x * CELLS_PER_BLOCK;
    const int cell_in_blk = tid >> 2;   // 0..63
    const int qg          = tid & 3;    // which float4 of Q=16
    const int c           = block_cell0 + cell_in_blk;
    const bool active     = (c < C);

    // ---- Phase 0: prefetch the streaming y tile into registers FIRST.
    // These addresses are independent of the gather; issuing them up front
    // keeps ~10 LDG.128 per thread in flight across the gather chain and
    // the barrier. __ldcs = evict-first: y has zero reuse, keep L2 for the
    // dof tables.
    float4 v[NB];
    if (active) {
        const float4* yv = reinterpret_cast<const float4*>(
                               y + (size_t)c * NB * QPTS) + qg;
        #pragma unroll
        for (int b = 0; b < NB; b++)
            v[b] = __ldcs(yv + b * (QPTS / 4));
    }

    // ---- Phase 1: gather local dofs, one thread per cell (tid < 64) ----
    if (tid < CELLS_PER_BLOCK) {
        int cc = block_cell0 + tid;
        if (cc < C) {
            // vertex dofs (DV=1)
            int v0 = __ldg(&faces[3 * cc + 0]);
            int v1 = __ldg(&faces[3 * cc + 1]);
            int v2 = __ldg(&faces[3 * cc + 2]);
            s_local[tid][0] = __ldg(&vertex_dofs[v0]);
            s_local[tid][1] = __ldg(&vertex_dofs[v1]);
            s_local[tid][2] = __ldg(&vertex_dofs[v2]);

            // edge dofs (DE=2), flip when orientation == 0
            #pragma unroll
            for (int e = 0; e < 3; e++) {
                int    eidx = __ldg(&f2e[3 * cc + e]);
                int    o    = __ldg(&orient[3 * cc + e]);
                float2 ed   = __ldg((const float2*)edge_dofs + eidx);
                float a = (o != 0) ? ed.x : ed.y;
                float b = (o != 0) ? ed.y : ed.x;
                s_local[tid][3 + 2 * e]     = a;
                s_local[tid][3 + 2 * e + 1] = b;
            }

            // face dof (DF=1)
            s_local[tid][9] = __ldg(&face_dofs[cc]);
        }
    }
    __syncthreads();

    if (!active) return;

    // ---- Phase 2: contraction on the prefetched registers ----
    float4 acc = make_float4(0.f, 0.f, 0.f, 0.f);
    #pragma unroll
    for (int b = 0; b < NB; b++) {
        float w = s_local[cell_in_blk][b];
        acc.x = fmaf(w, v[b].x, acc.x);
        acc.y = fmaf(w, v[b].y, acc.y);
        acc.z = fmaf(w, v[b].z, acc.z);
        acc.w = fmaf(w, v[b].w, acc.w);
    }

    __stcs(reinterpret_cast<float4*>(out + (size_t)c * QPTS) + qg, acc);
}

extern "C" void kernel_launch(void* const* d_in, const int* in_sizes, int n_in,
                              void* d_out, int out_size)
{
    const float* vertex_dofs = (const float*)d_in[0];
    const float* edge_dofs   = (const float*)d_in[1];
    const float* face_dofs   = (const float*)d_in[2];
    const float* y           = (const float*)d_in[3];
    const int*   faces       = (const int*)d_in[4];
    const int*   f2e         = (const int*)d_in[5];
    const int*   orient      = (const int*)d_in[6];
    float*       out         = (float*)d_out;

    // Derive C from y: [C, NB, Q]
    int C = in_sizes[3] / (NB * QPTS);

    int blocks = (C + CELLS_PER_BLOCK - 1) / CELLS_PER_BLOCK;
    quadfn_kernel<<<blocks, THREADS>>>(vertex_dofs, edge_dofs, face_dofs, y,
                                       faces, f2e, orient, out, C);
}

// round 6
// speedup vs baseline: 1.2662x; 1.1695x over previous
#include <cuda_runtime.h>
#include <stdint.h>

// Inputs (metadata order):
//  0: vertex_dofs  [V,1]  f32
//  1: edge_dofs    [E,2]  f32
//  2: face_dofs    [C,1]  f32
//  3: y            [C,10,16] f32
//  4: faces        [C,3]  i32
//  5: faces_to_edges [C,3] i32
//  6: edge_orientation [C,3] i32
// Output: [C,16] f32

#define NB 10
#define QPTS 16
#define THREADS 256  // 4 threads per cell, one float4 (4 quad pts) each

__global__ __launch_bounds__(THREADS)
void quadfn_kernel(const float* __restrict__ vertex_dofs,
                   const float* __restrict__ edge_dofs,
                   const float* __restrict__ face_dofs,
                   const float* __restrict__ y,
                   const int*   __restrict__ faces,
                   const int*   __restrict__ f2e,
                   const int*   __restrict__ orient,
                   float*       __restrict__ out,
                   int C)
{
    const int tid  = blockIdx.x * THREADS + threadIdx.x;
    const int c    = tid >> 2;          // one cell per 4-lane group
    const int lane = threadIdx.x & 31;
    const int qg   = lane & 3;          // which float4 of Q=16
    const int grp  = lane & ~3;         // group base lane within warp

    if (c >= C) return;                 // tail: whole 4-lane groups drop out

    // ---- Phase 0: prefetch the streaming y tile into registers FIRST.
    // 10 independent LDG.128 in flight across the entire gather+shuffle
    // chain. __ldcs = evict-first (y has zero reuse; keep L2 for dof tables).
    float4 v[NB];
    {
        const float4* yv = reinterpret_cast<const float4*>(
                               y + (size_t)c * NB * QPTS) + qg;
        #pragma unroll
        for (int b = 0; b < NB; b++)
            v[b] = __ldcs(yv + b * (QPTS / 4));
    }

    // ---- Phase 1: cooperative gather within the 4-lane group (no smem,
    // no __syncthreads — warps stay fully independent).
    // lanes 0..2: vertex dof qg + edge pair qg (orientation-resolved)
    // lane  3   : face dof
    float wv = 0.f, wa = 0.f, wb = 0.f, wf = 0.f;
    if (qg < 3) {
        int vidx = __ldg(&faces[3 * c + qg]);
        wv = __ldg(&vertex_dofs[vidx]);
        int    eidx = __ldg(&f2e[3 * c + qg]);
        int    o    = __ldg(&orient[3 * c + qg]);
        float2 ed   = __ldg((const float2*)edge_dofs + eidx);
        wa = (o != 0) ? ed.x : ed.y;   // first edge dof
        wb = (o != 0) ? ed.y : ed.x;   // second edge dof
    } else {
        wf = __ldg(&face_dofs[c]);
    }

    // ---- Phase 2: broadcast the 10 weights across the group via shuffle.
    const unsigned m = 0xffffffffu;
    float w0 = __shfl_sync(m, wv, grp + 0);
    float w1 = __shfl_sync(m, wv, grp + 1);
    float w2 = __shfl_sync(m, wv, grp + 2);
    float w3 = __shfl_sync(m, wa, grp + 0);
    float w4 = __shfl_sync(m, wb, grp + 0);
    float w5 = __shfl_sync(m, wa, grp + 1);
    float w6 = __shfl_sync(m, wb, grp + 1);
    float w7 = __shfl_sync(m, wa, grp + 2);
    float w8 = __shfl_sync(m, wb, grp + 2);
    float w9 = __shfl_sync(m, wf, grp + 3);

    // ---- Phase 3: contraction on the prefetched registers ----
    float4 acc;
    acc.x = w0 * v[0].x; acc.y = w0 * v[0].y;
    acc.z = w0 * v[0].z; acc.w = w0 * v[0].w;

    #define ACC(W, B)                         \
        acc.x = fmaf(W, v[B].x, acc.x);       \
        acc.y = fmaf(W, v[B].y, acc.y);       \
        acc.z = fmaf(W, v[B].z, acc.z);       \
        acc.w = fmaf(W, v[B].w, acc.w);
    ACC(w1, 1) ACC(w2, 2) ACC(w3, 3) ACC(w4, 4)
    ACC(w5, 5) ACC(w6, 6) ACC(w7, 7) ACC(w8, 8) ACC(w9, 9)
    #undef ACC

    __stcs(reinterpret_cast<float4*>(out + (size_t)c * QPTS) + qg, acc);
}

extern "C" void kernel_launch(void* const* d_in, const int* in_sizes, int n_in,
                              void* d_out, int out_size)
{
    const float* vertex_dofs = (const float*)d_in[0];
    const float* edge_dofs   = (const float*)d_in[1];
    const float* face_dofs   = (const float*)d_in[2];
    const float* y           = (const float*)d_in[3];
    const int*   faces       = (const int*)d_in[4];
    const int*   f2e         = (const int*)d_in[5];
    const int*   orient      = (const int*)d_in[6];
    float*       out         = (float*)d_out;

    // Derive C from y: [C, NB, Q]
    int C = in_sizes[3] / (NB * QPTS);

    int total_threads = C * 4;
    int blocks = (total_threads + THREADS - 1) / THREADS;
    quadfn_kernel<<<blocks, THREADS>>>(vertex_dofs, edge_dofs, face_dofs, y,
                                       faces, f2e, orient, out, C);
}